// round 13
// baseline (speedup 1.0000x reference)
#include <cuda_runtime.h>
#include <cuda_fp16.h>
#include <math.h>
#include <stdint.h>

// ---------------------------------------------------------------------------
// Problem constants
// ---------------------------------------------------------------------------
#define N_ROWS 131072
#define D 64
#define K 512
#define TILE_M 128
#define NTILES (N_ROWS / TILE_M)    // 1024
#define PADB 144                    // fp16 tile row stride in BYTES (64*2 + 16)
#define MAXCTA 256

// Output layout: [xn | xn | proto | cvae | pdl]
#define XN2_OFF   ((long)N_ROWS * D)
#define PROTO_OFF (2L * N_ROWS * D)
#define CVAE_OFF  (PROTO_OFF + (long)N_ROWS * K)
#define PDL_OFF   (CVAE_OFF + 1)

// Shared memory layout (bytes)
#define OFF_AHI   0                  // fp16 [128] rows x PADB (hi only)
#define OFF_WHI   18432              // fp16 [512] rows x PADB (resident)
#define OFF_WLO   92160
#define OFF_B2    165888             // f32 [512]
#define OFF_A2    167936             // f32 [128]
#define OFF_CMIN  168448             // u32 [512]  (persistent across tiles)
#define OFF_RMIN  170496             // u32 [128]  (per tile)
#define OFF_XS    171008             // f32 x staging [128][64] = 32768 (cp.async)
#define SMEM_TOTAL 203776

// Device scratch (no allocations allowed)
__device__ float        g_row_partial[NTILES];
__device__ unsigned int g_colmin_cta[MAXCTA * K];   // per-CTA col mins (plain stores)

// ---------------------------------------------------------------------------
// Helpers (sm_80-level PTX only: ldmatrix + mma.sync + cp.async)
// ---------------------------------------------------------------------------
__device__ __forceinline__ uint32_t smem_u32(const void* p) {
    uint32_t a;
    asm("{ .reg .u64 t; cvta.to.shared.u64 t, %1; cvt.u32.u64 %0, t; }" : "=r"(a) : "l"(p));
    return a;
}
__device__ __forceinline__ void ldsm_x4(uint32_t* r, uint32_t addr) {
    asm volatile("ldmatrix.sync.aligned.m8n8.x4.shared.b16 {%0,%1,%2,%3}, [%4];"
                 : "=r"(r[0]), "=r"(r[1]), "=r"(r[2]), "=r"(r[3]) : "r"(addr));
}
__device__ __forceinline__ void mma_f16(float* d, const uint32_t* a, uint32_t b0, uint32_t b1) {
    asm volatile("mma.sync.aligned.m16n8k16.row.col.f32.f16.f16.f32 "
                 "{%0,%1,%2,%3}, {%4,%5,%6,%7}, {%8,%9}, {%0,%1,%2,%3};"
                 : "+f"(d[0]), "+f"(d[1]), "+f"(d[2]), "+f"(d[3])
                 : "r"(a[0]), "r"(a[1]), "r"(a[2]), "r"(a[3]), "r"(b0), "r"(b1));
}
__device__ __forceinline__ void cp_async16(uint32_t saddr, const void* gptr) {
    asm volatile("cp.async.cg.shared.global [%0], [%1], 16;"
                 :: "r"(saddr), "l"(gptr) : "memory");
}
#define CP_COMMIT()   asm volatile("cp.async.commit_group;" ::: "memory")
#define CP_WAIT_ALL() asm volatile("cp.async.wait_all;" ::: "memory")

// ---------------------------------------------------------------------------
// Main: PERSISTENT CTAs, no init kernel. Per-CTA one-time: build fp16 W
// hi/lo tiles + b2 from global W. Per tile: cp.async-staged x -> normalize ->
// xn x2 -> fp16 A-hi tile -> 2-product HMMA GEMM (B-frag prefetch, product-
// major interleave) -> register epilogue (stcs proto + z-mins) -> warp reduce.
// ---------------------------------------------------------------------------
__global__ __launch_bounds__(256, 1)
void swav_main_kernel(const float* __restrict__ x, const float* __restrict__ W,
                      float* __restrict__ out, int nsm) {
    extern __shared__ __align__(16) char sm[];
    float*        b2s    = (float*)(sm + OFF_B2);
    float*        a2s    = (float*)(sm + OFF_A2);
    unsigned int* cmin_s = (unsigned int*)(sm + OFF_CMIN);
    unsigned int* rmin_s = (unsigned int*)(sm + OFF_RMIN);

    const uint32_t sb  = smem_u32(sm);
    const int t   = threadIdx.x;
    const int lid = t & 31;
    const int wid = t >> 5;

    // ---- One-time: W -> fp16 hi/lo smem tiles + b2 (from global, L2-hot) ----
    #pragma unroll
    for (int rr = 0; rr < 2; ++rr) {
        int r = t + rr * 256;
        const float4* wr = (const float4*)(W + (long)r * D);
        float b2 = 0.f;
        #pragma unroll
        for (int j = 0; j < 16; ++j) {
            float4 w4 = wr[j];
            b2 = fmaf(w4.x, w4.x, fmaf(w4.y, w4.y,
                 fmaf(w4.z, w4.z, fmaf(w4.w, w4.w, b2))));
            __half hx = __float2half_rn(w4.x), hy = __float2half_rn(w4.y);
            __half hz = __float2half_rn(w4.z), hw = __float2half_rn(w4.w);
            __half2 hp0 = __halves2half2(hx, hy);
            __half2 hp1 = __halves2half2(hz, hw);
            __half2 lp0 = __halves2half2(__float2half_rn(w4.x - __half2float(hx)),
                                         __float2half_rn(w4.y - __half2float(hy)));
            __half2 lp1 = __halves2half2(__float2half_rn(w4.z - __half2float(hz)),
                                         __float2half_rn(w4.w - __half2float(hw)));
            *(uint2*)(sm + OFF_WHI + r * PADB + j * 8) =
                make_uint2(*(unsigned*)&hp0, *(unsigned*)&hp1);
            *(uint2*)(sm + OFF_WLO + r * PADB + j * 8) =
                make_uint2(*(unsigned*)&lp0, *(unsigned*)&lp1);
        }
        b2s[r] = b2;
        cmin_s[r] = 0x7F800000u;
    }

    // Prefetch x for first tile
    {
        int tile0 = blockIdx.x;
        if (tile0 < NTILES) {
            const char* gx = (const char*)(x + (long)tile0 * TILE_M * D);
            #pragma unroll
            for (int i = 0; i < 8; ++i) {
                int idx = t + i * 256;
                cp_async16(sb + OFF_XS + idx * 16, gx + (long)idx * 16);
            }
        }
        CP_COMMIT();
    }

    // ldmatrix lane addressing (tile-invariant)
    const int wy = wid & 3, wx = wid >> 2;
    const int m0 = wy * 32;
    const uint32_t a_off    = (uint32_t)(m0 + (lid & 15)) * PADB + ((lid >> 4) * 16);
    const uint32_t aaddr_hi = sb + OFF_AHI + a_off;
    const uint32_t b_rowi   = ((lid >> 4) << 3) + (lid & 7);
    const uint32_t b_koff   = ((lid >> 3) & 1) * 16;

    // ================= persistent tile loop =================
    for (int tile = blockIdx.x; tile < NTILES; tile += nsm) {
        const long row0 = (long)tile * TILE_M;

        CP_WAIT_ALL();
        __syncthreads();   // staged x ready; W tiles ready (first iter)

        // ---- read staged x into regs ----
        float4 v[8]; float s[8];
        #pragma unroll
        for (int i = 0; i < 8; ++i) {
            int idx = t + i * 256;                    // [128 rows][16 float4]
            v[i] = *(const float4*)(sm + OFF_XS + idx * 16);
            s[i] = fmaf(v[i].x, v[i].x, fmaf(v[i].y, v[i].y,
                    fmaf(v[i].z, v[i].z, v[i].w * v[i].w)));
        }
        __syncthreads();   // staging consumed -> safe to overwrite

        // ---- prefetch next tile's x (overlaps with pack + GEMM) ----
        {
            int nxt = tile + nsm;
            if (nxt < NTILES) {
                const char* gx = (const char*)(x + (long)nxt * TILE_M * D);
                #pragma unroll
                for (int i = 0; i < 8; ++i) {
                    int idx = t + i * 256;
                    cp_async16(sb + OFF_XS + idx * 16, gx + (long)idx * 16);
                }
            }
            CP_COMMIT();
        }

        // ---- normalize, write xn x2, build A hi tile (fp16) ----
        #pragma unroll
        for (int m = 1; m < 16; m <<= 1)
            #pragma unroll
            for (int i = 0; i < 8; ++i)
                s[i] += __shfl_xor_sync(0xffffffffu, s[i], m);
        {
            float4* xn1 = (float4*)(out + row0 * D);
            float4* xn2 = (float4*)(out + XN2_OFF + row0 * D);
            #pragma unroll
            for (int i = 0; i < 8; ++i) {
                int idx = t + i * 256;
                int r = idx >> 4, c = idx & 15;
                float inv = 1.0f / fmaxf(sqrtf(s[i]), 1e-12f);
                float4 w4 = make_float4(v[i].x * inv, v[i].y * inv,
                                        v[i].z * inv, v[i].w * inv);
                xn1[idx] = w4;
                xn2[idx] = w4;
                if ((t & 15) == 0) a2s[r] = s[i] * inv * inv;

                __half2 hp0 = __floats2half2_rn(w4.x, w4.y);
                __half2 hp1 = __floats2half2_rn(w4.z, w4.w);
                *(uint2*)(sm + OFF_AHI + r * PADB + c * 8) =
                    make_uint2(*(unsigned*)&hp0, *(unsigned*)&hp1);
            }
        }
        if (t < TILE_M) rmin_s[t] = 0x7F800000u;
        __syncthreads();

        // ---- 2-product HMMA GEMM + epilogue, two column halves ----
        float a2r[2][2];
        #pragma unroll
        for (int mf = 0; mf < 2; ++mf) {
            a2r[mf][0] = a2s[m0 + mf * 16 + (lid >> 2)];
            a2r[mf][1] = a2s[m0 + mf * 16 + (lid >> 2) + 8];
        }
        float rowmin[4];
        #pragma unroll
        for (int j = 0; j < 4; ++j) rowmin[j] = 3.0e38f;

        for (int h = 0; h < 2; ++h) {
            const int nb = h * 256 + wx * 128;
            float acc[2][16][4];
            #pragma unroll
            for (int mf = 0; mf < 2; ++mf)
                #pragma unroll
                for (int p = 0; p < 16; ++p)
                    #pragma unroll
                    for (int q = 0; q < 4; ++q) acc[mf][p][q] = 0.f;

            #pragma unroll 1
            for (int k = 0; k < 4; ++k) {
                const uint32_t ka = (uint32_t)k * 32;
                uint32_t ah[2][4];
                ldsm_x4(ah[0], aaddr_hi + ka);
                ldsm_x4(ah[1], aaddr_hi + 16 * PADB + ka);
                // B-fragment prefetch pipeline: load p+1 before p's MMAs.
                uint32_t bh[4], bl[4];
                {
                    uint32_t b0 = sb + OFF_WHI +
                        (uint32_t)(nb + b_rowi) * PADB + b_koff + ka;
                    ldsm_x4(bh, b0);
                    ldsm_x4(bl, b0 + (OFF_WLO - OFF_WHI));
                }
                #pragma unroll
                for (int p = 0; p < 8; ++p) {
                    uint32_t nh[4], nl[4];
                    if (p < 7) {
                        uint32_t bn = sb + OFF_WHI +
                            (uint32_t)(nb + (p + 1) * 16 + b_rowi) * PADB + b_koff + ka;
                        ldsm_x4(nh, bn);
                        ldsm_x4(nl, bn + (OFF_WLO - OFF_WHI));
                    }
                    // Product-major interleave: 4 independent accumulator chains
                    mma_f16(acc[0][2 * p],     ah[0], bh[0], bh[1]);   // hh
                    mma_f16(acc[0][2 * p + 1], ah[0], bh[2], bh[3]);
                    mma_f16(acc[1][2 * p],     ah[1], bh[0], bh[1]);
                    mma_f16(acc[1][2 * p + 1], ah[1], bh[2], bh[3]);
                    mma_f16(acc[0][2 * p],     ah[0], bl[0], bl[1]);   // hl
                    mma_f16(acc[0][2 * p + 1], ah[0], bl[2], bl[3]);
                    mma_f16(acc[1][2 * p],     ah[1], bl[0], bl[1]);
                    mma_f16(acc[1][2 * p + 1], ah[1], bl[2], bl[3]);
                    #pragma unroll
                    for (int q = 0; q < 4; ++q) { bh[q] = nh[q]; bl[q] = nl[q]; }
                }
            }

            // Epilogue: streaming proto stores + z-mins, all from registers
            #pragma unroll
            for (int p = 0; p < 16; ++p) {
                const int c = nb + p * 8 + 2 * (lid & 3);
                const float b2c0 = b2s[c], b2c1 = b2s[c + 1];
                float cm0 = 3.0e38f, cm1 = 3.0e38f;
                #pragma unroll
                for (int mf = 0; mf < 2; ++mf) {
                    float* d = acc[mf][p];
                    const int r0 = m0 + mf * 16 + (lid >> 2);
                    __stcs((float2*)(out + PROTO_OFF + (row0 + r0) * (long)K + c),
                           make_float2(d[0], d[1]));
                    __stcs((float2*)(out + PROTO_OFF + (row0 + r0 + 8) * (long)K + c),
                           make_float2(d[2], d[3]));
                    float z0 = fmaxf(fmaf(-2.f, d[0], a2r[mf][0] + b2c0), 0.f);
                    float z1 = fmaxf(fmaf(-2.f, d[1], a2r[mf][0] + b2c1), 0.f);
                    float z2 = fmaxf(fmaf(-2.f, d[2], a2r[mf][1] + b2c0), 0.f);
                    float z3 = fmaxf(fmaf(-2.f, d[3], a2r[mf][1] + b2c1), 0.f);
                    rowmin[mf * 2]     = fminf(rowmin[mf * 2],     fminf(z0, z1));
                    rowmin[mf * 2 + 1] = fminf(rowmin[mf * 2 + 1], fminf(z2, z3));
                    cm0 = fminf(cm0, fminf(z0, z2));
                    cm1 = fminf(cm1, fminf(z1, z3));
                }
                #pragma unroll
                for (int o = 4; o < 32; o <<= 1) {
                    cm0 = fminf(cm0, __shfl_xor_sync(0xffffffffu, cm0, o));
                    cm1 = fminf(cm1, __shfl_xor_sync(0xffffffffu, cm1, o));
                }
                if (lid < 4) {
                    atomicMin(&cmin_s[c],     __float_as_uint(cm0));
                    atomicMin(&cmin_s[c + 1], __float_as_uint(cm1));
                }
            }
        }

        // Row-min: quad reduce then smem atomics
        #pragma unroll
        for (int o = 1; o < 4; o <<= 1)
            #pragma unroll
            for (int j = 0; j < 4; ++j)
                rowmin[j] = fminf(rowmin[j], __shfl_xor_sync(0xffffffffu, rowmin[j], o));
        if ((lid & 3) == 0) {
            const int rq = lid >> 2;
            atomicMin(&rmin_s[m0 + rq],      __float_as_uint(rowmin[0]));
            atomicMin(&rmin_s[m0 + rq + 8],  __float_as_uint(rowmin[1]));
            atomicMin(&rmin_s[m0 + 16 + rq], __float_as_uint(rowmin[2]));
            atomicMin(&rmin_s[m0 + 24 + rq], __float_as_uint(rowmin[3]));
        }
        __syncthreads();

        // Per-tile row reduction: single warp, shuffle tree
        if (wid == 0) {
            float rs = 0.f;
            #pragma unroll
            for (int i = 0; i < 4; ++i)
                rs += sqrtf(fmaxf(__uint_as_float(rmin_s[lid * 4 + i]), 1e-12f));
            #pragma unroll
            for (int o = 16; o > 0; o >>= 1)
                rs += __shfl_xor_sync(0xffffffffu, rs, o);
            if (lid == 0) g_row_partial[tile] = rs;
        }
    }

    // ---- per-CTA column mins -> plain global stores (no init needed) ----
    g_colmin_cta[blockIdx.x * K + t]       = cmin_s[t];
    g_colmin_cta[blockIdx.x * K + 256 + t] = cmin_s[t + 256];
}

// ---------------------------------------------------------------------------
// Final: deterministic reductions + scalar outputs
// ---------------------------------------------------------------------------
__global__ void swav_final_kernel(const float* __restrict__ recon,
                                  const float* __restrict__ kl,
                                  const float* __restrict__ mmd,
                                  float* __restrict__ out, int nct) {
    __shared__ float red[K];
    int t = threadIdx.x;  // 512 threads
    float s = 0.f;
    for (int i = t; i < NTILES; i += K) s += g_row_partial[i];
    red[t] = s;
    __syncthreads();
    for (int st = 256; st > 0; st >>= 1) { if (t < st) red[t] += red[t + st]; __syncthreads(); }
    float rowsum = red[0];
    __syncthreads();

    unsigned int m = 0x7F800000u;
    for (int i = 0; i < nct; ++i)
        m = min(m, g_colmin_cta[i * K + t]);
    red[t] = sqrtf(fmaxf(__uint_as_float(m), 1e-12f));
    __syncthreads();
    for (int st = 256; st > 0; st >>= 1) { if (t < st) red[t] += red[t + st]; __syncthreads(); }

    if (t == 0) {
        float pdl = 0.5f * (rowsum / (float)N_ROWS) + 0.5f * (red[0] / (float)K);
        out[CVAE_OFF] = recon[0] + 0.5f * kl[0] + mmd[0];
        out[PDL_OFF]  = pdl;
    }
}

// ---------------------------------------------------------------------------
extern "C" void kernel_launch(void* const* d_in, const int* in_sizes, int n_in,
                              void* d_out, int out_size) {
    const float* x     = (const float*)d_in[0];
    const float* W     = (const float*)d_in[1];
    const float* recon = (const float*)d_in[2];
    const float* kl    = (const float*)d_in[3];
    const float* mmd   = (const float*)d_in[4];
    float* out = (float*)d_out;

    static int nsm = 0;
    if (nsm == 0) {
        cudaDeviceGetAttribute(&nsm, cudaDevAttrMultiProcessorCount, 0);
        if (nsm <= 0) nsm = 148;
        if (nsm > MAXCTA) nsm = MAXCTA;
        cudaFuncSetAttribute(swav_main_kernel,
                             cudaFuncAttributeMaxDynamicSharedMemorySize, SMEM_TOTAL);
    }

    swav_main_kernel<<<nsm, 256, SMEM_TOTAL>>>(x, W, out, nsm);
    swav_final_kernel<<<1, K>>>(recon, kl, mmd, out, nsm);
}

// round 14
// speedup vs baseline: 1.0354x; 1.0354x over previous
#include <cuda_runtime.h>
#include <cuda_fp16.h>
#include <math.h>
#include <stdint.h>

// ---------------------------------------------------------------------------
// Problem constants
// ---------------------------------------------------------------------------
#define N_ROWS 131072
#define D 64
#define K 512
#define TILE_M 128
#define NTILES (N_ROWS / TILE_M)    // 1024
#define PADB 144                    // fp16 tile row stride in BYTES (64*2 + 16)
#define MAXCTA 256
#define THREADS 512

// Output layout: [xn | xn | proto | cvae | pdl]
#define XN2_OFF   ((long)N_ROWS * D)
#define PROTO_OFF (2L * N_ROWS * D)
#define CVAE_OFF  (PROTO_OFF + (long)N_ROWS * K)
#define PDL_OFF   (CVAE_OFF + 1)

// Shared memory layout (bytes)
#define OFF_AHI   0                  // fp16 [128] rows x PADB (hi only)
#define OFF_WHI   18432              // fp16 [512] rows x PADB (resident)
#define OFF_WLO   92160
#define OFF_B2    165888             // f32 [512]
#define OFF_A2    167936             // f32 [128]
#define OFF_CMIN  168448             // u32 [512]  (persistent across tiles)
#define OFF_RMIN  170496             // u32 [128]  (per tile)
#define OFF_XS    171008             // f32 x staging [128][64] = 32768 (cp.async)
#define SMEM_TOTAL 203776

// Device scratch (no allocations allowed)
__device__ float        g_row_partial[NTILES];
__device__ unsigned int g_colmin_cta[MAXCTA * K];   // per-CTA col mins (plain stores)

// ---------------------------------------------------------------------------
// Helpers (sm_80-level PTX only: ldmatrix + mma.sync + cp.async)
// ---------------------------------------------------------------------------
__device__ __forceinline__ uint32_t smem_u32(const void* p) {
    uint32_t a;
    asm("{ .reg .u64 t; cvta.to.shared.u64 t, %1; cvt.u32.u64 %0, t; }" : "=r"(a) : "l"(p));
    return a;
}
__device__ __forceinline__ void ldsm_x4(uint32_t* r, uint32_t addr) {
    asm volatile("ldmatrix.sync.aligned.m8n8.x4.shared.b16 {%0,%1,%2,%3}, [%4];"
                 : "=r"(r[0]), "=r"(r[1]), "=r"(r[2]), "=r"(r[3]) : "r"(addr));
}
__device__ __forceinline__ void mma_f16(float* d, const uint32_t* a, uint32_t b0, uint32_t b1) {
    asm volatile("mma.sync.aligned.m16n8k16.row.col.f32.f16.f16.f32 "
                 "{%0,%1,%2,%3}, {%4,%5,%6,%7}, {%8,%9}, {%0,%1,%2,%3};"
                 : "+f"(d[0]), "+f"(d[1]), "+f"(d[2]), "+f"(d[3])
                 : "r"(a[0]), "r"(a[1]), "r"(a[2]), "r"(a[3]), "r"(b0), "r"(b1));
}
__device__ __forceinline__ void cp_async16(uint32_t saddr, const void* gptr) {
    asm volatile("cp.async.cg.shared.global [%0], [%1], 16;"
                 :: "r"(saddr), "l"(gptr) : "memory");
}
#define CP_COMMIT()   asm volatile("cp.async.commit_group;" ::: "memory")
#define CP_WAIT_ALL() asm volatile("cp.async.wait_all;" ::: "memory")

// ---------------------------------------------------------------------------
// Main: PERSISTENT CTAs, 512 threads (16 warps -> 4/SMSP for MMA/epilogue
// overlap). One-time: W -> fp16 hi/lo tiles + b2. Per tile: staged x ->
// normalize -> xn x2 -> fp16 A-hi -> 2-product HMMA GEMM (warp tile 32x64,
// 2 passes) -> register epilogue -> reductions.
// ---------------------------------------------------------------------------
__global__ __launch_bounds__(THREADS, 1)
void swav_main_kernel(const float* __restrict__ x, const float* __restrict__ W,
                      float* __restrict__ out, int nsm) {
    extern __shared__ __align__(16) char sm[];
    float*        b2s    = (float*)(sm + OFF_B2);
    float*        a2s    = (float*)(sm + OFF_A2);
    unsigned int* cmin_s = (unsigned int*)(sm + OFF_CMIN);
    unsigned int* rmin_s = (unsigned int*)(sm + OFF_RMIN);

    const uint32_t sb  = smem_u32(sm);
    const int t   = threadIdx.x;
    const int lid = t & 31;
    const int wid = t >> 5;

    // ---- One-time: W -> fp16 hi/lo smem tiles + b2 (one row per thread) ----
    {
        const int r = t;
        const float4* wr = (const float4*)(W + (long)r * D);
        float b2 = 0.f;
        #pragma unroll
        for (int j = 0; j < 16; ++j) {
            float4 w4 = wr[j];
            b2 = fmaf(w4.x, w4.x, fmaf(w4.y, w4.y,
                 fmaf(w4.z, w4.z, fmaf(w4.w, w4.w, b2))));
            __half hx = __float2half_rn(w4.x), hy = __float2half_rn(w4.y);
            __half hz = __float2half_rn(w4.z), hw = __float2half_rn(w4.w);
            __half2 hp0 = __halves2half2(hx, hy);
            __half2 hp1 = __halves2half2(hz, hw);
            __half2 lp0 = __halves2half2(__float2half_rn(w4.x - __half2float(hx)),
                                         __float2half_rn(w4.y - __half2float(hy)));
            __half2 lp1 = __halves2half2(__float2half_rn(w4.z - __half2float(hz)),
                                         __float2half_rn(w4.w - __half2float(hw)));
            *(uint2*)(sm + OFF_WHI + r * PADB + j * 8) =
                make_uint2(*(unsigned*)&hp0, *(unsigned*)&hp1);
            *(uint2*)(sm + OFF_WLO + r * PADB + j * 8) =
                make_uint2(*(unsigned*)&lp0, *(unsigned*)&lp1);
        }
        b2s[r] = b2;
        cmin_s[r] = 0x7F800000u;
    }

    // Prefetch x for first tile
    {
        int tile0 = blockIdx.x;
        if (tile0 < NTILES) {
            const char* gx = (const char*)(x + (long)tile0 * TILE_M * D);
            #pragma unroll
            for (int i = 0; i < 4; ++i) {
                int idx = t + i * THREADS;
                cp_async16(sb + OFF_XS + idx * 16, gx + (long)idx * 16);
            }
        }
        CP_COMMIT();
    }

    // ldmatrix lane addressing (tile-invariant). 16 warps: wy row group,
    // wx in 0..3 -> 128-col strip; 2 passes of 64 cols inside strip.
    const int wy = wid & 3, wx = wid >> 2;
    const int m0 = wy * 32;
    const uint32_t a_off    = (uint32_t)(m0 + (lid & 15)) * PADB + ((lid >> 4) * 16);
    const uint32_t aaddr_hi = sb + OFF_AHI + a_off;
    const uint32_t b_rowi   = ((lid >> 4) << 3) + (lid & 7);
    const uint32_t b_koff   = ((lid >> 3) & 1) * 16;

    // ================= persistent tile loop =================
    for (int tile = blockIdx.x; tile < NTILES; tile += nsm) {
        const long row0 = (long)tile * TILE_M;

        CP_WAIT_ALL();
        __syncthreads();   // staged x ready; W tiles ready (first iter)

        // ---- read staged x into regs ----
        float4 v[4]; float s[4];
        #pragma unroll
        for (int i = 0; i < 4; ++i) {
            int idx = t + i * THREADS;                // [128 rows][16 float4]
            v[i] = *(const float4*)(sm + OFF_XS + idx * 16);
            s[i] = fmaf(v[i].x, v[i].x, fmaf(v[i].y, v[i].y,
                    fmaf(v[i].z, v[i].z, v[i].w * v[i].w)));
        }
        __syncthreads();   // staging consumed -> safe to overwrite

        // ---- prefetch next tile's x (overlaps with pack + GEMM) ----
        {
            int nxt = tile + nsm;
            if (nxt < NTILES) {
                const char* gx = (const char*)(x + (long)nxt * TILE_M * D);
                #pragma unroll
                for (int i = 0; i < 4; ++i) {
                    int idx = t + i * THREADS;
                    cp_async16(sb + OFF_XS + idx * 16, gx + (long)idx * 16);
                }
            }
            CP_COMMIT();
        }

        // ---- normalize (16 lanes per row), write xn x2, build A hi tile ----
        #pragma unroll
        for (int m = 1; m < 16; m <<= 1)
            #pragma unroll
            for (int i = 0; i < 4; ++i)
                s[i] += __shfl_xor_sync(0xffffffffu, s[i], m);
        {
            float4* xn1 = (float4*)(out + row0 * D);
            float4* xn2 = (float4*)(out + XN2_OFF + row0 * D);
            #pragma unroll
            for (int i = 0; i < 4; ++i) {
                int idx = t + i * THREADS;
                int r = idx >> 4, c = idx & 15;
                float inv = 1.0f / fmaxf(sqrtf(s[i]), 1e-12f);
                float4 w4 = make_float4(v[i].x * inv, v[i].y * inv,
                                        v[i].z * inv, v[i].w * inv);
                xn1[idx] = w4;
                xn2[idx] = w4;
                if ((t & 15) == 0) a2s[r] = s[i] * inv * inv;

                __half2 hp0 = __floats2half2_rn(w4.x, w4.y);
                __half2 hp1 = __floats2half2_rn(w4.z, w4.w);
                *(uint2*)(sm + OFF_AHI + r * PADB + c * 8) =
                    make_uint2(*(unsigned*)&hp0, *(unsigned*)&hp1);
            }
        }
        if (t < TILE_M) rmin_s[t] = 0x7F800000u;
        __syncthreads();

        // ---- 2-product HMMA GEMM + epilogue, 2 passes of 64 cols ----
        float a2r[2][2];
        #pragma unroll
        for (int mf = 0; mf < 2; ++mf) {
            a2r[mf][0] = a2s[m0 + mf * 16 + (lid >> 2)];
            a2r[mf][1] = a2s[m0 + mf * 16 + (lid >> 2) + 8];
        }
        float rowmin[4];
        #pragma unroll
        for (int j = 0; j < 4; ++j) rowmin[j] = 3.0e38f;

        #pragma unroll 1
        for (int h = 0; h < 2; ++h) {
            const int nb = wx * 128 + h * 64;
            float acc[2][8][4];
            #pragma unroll
            for (int mf = 0; mf < 2; ++mf)
                #pragma unroll
                for (int p = 0; p < 8; ++p)
                    #pragma unroll
                    for (int q = 0; q < 4; ++q) acc[mf][p][q] = 0.f;

            #pragma unroll 1
            for (int k = 0; k < 4; ++k) {
                const uint32_t ka = (uint32_t)k * 32;
                uint32_t ah[2][4];
                ldsm_x4(ah[0], aaddr_hi + ka);
                ldsm_x4(ah[1], aaddr_hi + 16 * PADB + ka);
                // B-fragment prefetch pipeline: load pg+1 before pg's MMAs.
                uint32_t bh[4], bl[4];
                {
                    uint32_t b0 = sb + OFF_WHI +
                        (uint32_t)(nb + b_rowi) * PADB + b_koff + ka;
                    ldsm_x4(bh, b0);
                    ldsm_x4(bl, b0 + (OFF_WLO - OFF_WHI));
                }
                #pragma unroll
                for (int pg = 0; pg < 4; ++pg) {     // 16-col groups
                    uint32_t nh[4], nl[4];
                    if (pg < 3) {
                        uint32_t bn = sb + OFF_WHI +
                            (uint32_t)(nb + (pg + 1) * 16 + b_rowi) * PADB + b_koff + ka;
                        ldsm_x4(nh, bn);
                        ldsm_x4(nl, bn + (OFF_WLO - OFF_WHI));
                    }
                    // Product-major interleave: 4 independent accumulator chains
                    mma_f16(acc[0][2 * pg],     ah[0], bh[0], bh[1]);   // hh
                    mma_f16(acc[0][2 * pg + 1], ah[0], bh[2], bh[3]);
                    mma_f16(acc[1][2 * pg],     ah[1], bh[0], bh[1]);
                    mma_f16(acc[1][2 * pg + 1], ah[1], bh[2], bh[3]);
                    mma_f16(acc[0][2 * pg],     ah[0], bl[0], bl[1]);   // hl
                    mma_f16(acc[0][2 * pg + 1], ah[0], bl[2], bl[3]);
                    mma_f16(acc[1][2 * pg],     ah[1], bl[0], bl[1]);
                    mma_f16(acc[1][2 * pg + 1], ah[1], bl[2], bl[3]);
                    #pragma unroll
                    for (int q = 0; q < 4; ++q) { bh[q] = nh[q]; bl[q] = nl[q]; }
                }
            }

            // Epilogue: streaming proto stores + z-mins, from registers
            #pragma unroll
            for (int p = 0; p < 8; ++p) {
                const int c = nb + p * 8 + 2 * (lid & 3);
                const float b2c0 = b2s[c], b2c1 = b2s[c + 1];
                float cm0 = 3.0e38f, cm1 = 3.0e38f;
                #pragma unroll
                for (int mf = 0; mf < 2; ++mf) {
                    float* d = acc[mf][p];
                    const int r0 = m0 + mf * 16 + (lid >> 2);
                    __stcs((float2*)(out + PROTO_OFF + (row0 + r0) * (long)K + c),
                           make_float2(d[0], d[1]));
                    __stcs((float2*)(out + PROTO_OFF + (row0 + r0 + 8) * (long)K + c),
                           make_float2(d[2], d[3]));
                    float z0 = fmaxf(fmaf(-2.f, d[0], a2r[mf][0] + b2c0), 0.f);
                    float z1 = fmaxf(fmaf(-2.f, d[1], a2r[mf][0] + b2c1), 0.f);
                    float z2 = fmaxf(fmaf(-2.f, d[2], a2r[mf][1] + b2c0), 0.f);
                    float z3 = fmaxf(fmaf(-2.f, d[3], a2r[mf][1] + b2c1), 0.f);
                    rowmin[mf * 2]     = fminf(rowmin[mf * 2],     fminf(z0, z1));
                    rowmin[mf * 2 + 1] = fminf(rowmin[mf * 2 + 1], fminf(z2, z3));
                    cm0 = fminf(cm0, fminf(z0, z2));
                    cm1 = fminf(cm1, fminf(z1, z3));
                }
                #pragma unroll
                for (int o = 4; o < 32; o <<= 1) {
                    cm0 = fminf(cm0, __shfl_xor_sync(0xffffffffu, cm0, o));
                    cm1 = fminf(cm1, __shfl_xor_sync(0xffffffffu, cm1, o));
                }
                if (lid < 4) {
                    atomicMin(&cmin_s[c],     __float_as_uint(cm0));
                    atomicMin(&cmin_s[c + 1], __float_as_uint(cm1));
                }
            }
        }

        // Row-min: quad reduce then smem atomics
        #pragma unroll
        for (int o = 1; o < 4; o <<= 1)
            #pragma unroll
            for (int j = 0; j < 4; ++j)
                rowmin[j] = fminf(rowmin[j], __shfl_xor_sync(0xffffffffu, rowmin[j], o));
        if ((lid & 3) == 0) {
            const int rq = lid >> 2;
            atomicMin(&rmin_s[m0 + rq],      __float_as_uint(rowmin[0]));
            atomicMin(&rmin_s[m0 + rq + 8],  __float_as_uint(rowmin[1]));
            atomicMin(&rmin_s[m0 + 16 + rq], __float_as_uint(rowmin[2]));
            atomicMin(&rmin_s[m0 + 24 + rq], __float_as_uint(rowmin[3]));
        }
        __syncthreads();

        // Per-tile row reduction: single warp, shuffle tree
        if (wid == 0) {
            float rs = 0.f;
            #pragma unroll
            for (int i = 0; i < 4; ++i)
                rs += sqrtf(fmaxf(__uint_as_float(rmin_s[lid * 4 + i]), 1e-12f));
            #pragma unroll
            for (int o = 16; o > 0; o >>= 1)
                rs += __shfl_xor_sync(0xffffffffu, rs, o);
            if (lid == 0) g_row_partial[tile] = rs;
        }
    }

    // ---- per-CTA column mins -> plain global stores (no init needed) ----
    g_colmin_cta[blockIdx.x * K + t] = cmin_s[t];
}

// ---------------------------------------------------------------------------
// Final: deterministic reductions + scalar outputs (8-way ILP colmin scan)
// ---------------------------------------------------------------------------
__global__ void swav_final_kernel(const float* __restrict__ recon,
                                  const float* __restrict__ kl,
                                  const float* __restrict__ mmd,
                                  float* __restrict__ out, int nct) {
    __shared__ float red[K];
    int t = threadIdx.x;  // 512 threads
    float s = 0.f;
    for (int i = t; i < NTILES; i += K) s += g_row_partial[i];
    red[t] = s;
    __syncthreads();
    for (int st = 256; st > 0; st >>= 1) { if (t < st) red[t] += red[t + st]; __syncthreads(); }
    float rowsum = red[0];
    __syncthreads();

    // 8 independent min chains -> MLP 8
    unsigned int m[8];
    #pragma unroll
    for (int j = 0; j < 8; ++j) m[j] = 0x7F800000u;
    int i = 0;
    for (; i + 8 <= nct; i += 8) {
        #pragma unroll
        for (int j = 0; j < 8; ++j)
            m[j] = min(m[j], g_colmin_cta[(i + j) * K + t]);
    }
    for (; i < nct; ++i) m[0] = min(m[0], g_colmin_cta[i * K + t]);
    #pragma unroll
    for (int j = 1; j < 8; ++j) m[0] = min(m[0], m[j]);

    red[t] = sqrtf(fmaxf(__uint_as_float(m[0]), 1e-12f));
    __syncthreads();
    for (int st = 256; st > 0; st >>= 1) { if (t < st) red[t] += red[t + st]; __syncthreads(); }

    if (t == 0) {
        float pdl = 0.5f * (rowsum / (float)N_ROWS) + 0.5f * (red[0] / (float)K);
        out[CVAE_OFF] = recon[0] + 0.5f * kl[0] + mmd[0];
        out[PDL_OFF]  = pdl;
    }
}

// ---------------------------------------------------------------------------
extern "C" void kernel_launch(void* const* d_in, const int* in_sizes, int n_in,
                              void* d_out, int out_size) {
    const float* x     = (const float*)d_in[0];
    const float* W     = (const float*)d_in[1];
    const float* recon = (const float*)d_in[2];
    const float* kl    = (const float*)d_in[3];
    const float* mmd   = (const float*)d_in[4];
    float* out = (float*)d_out;

    static int nsm = 0;
    if (nsm == 0) {
        cudaDeviceGetAttribute(&nsm, cudaDevAttrMultiProcessorCount, 0);
        if (nsm <= 0) nsm = 148;
        if (nsm > MAXCTA) nsm = MAXCTA;
        cudaFuncSetAttribute(swav_main_kernel,
                             cudaFuncAttributeMaxDynamicSharedMemorySize, SMEM_TOTAL);
    }

    swav_main_kernel<<<nsm, THREADS, SMEM_TOTAL>>>(x, W, out, nsm);
    swav_final_kernel<<<1, K>>>(recon, kl, mmd, out, nsm);
}

// round 15
// speedup vs baseline: 1.0414x; 1.0058x over previous
#include <cuda_runtime.h>
#include <cuda_fp16.h>
#include <math.h>
#include <stdint.h>

// ---------------------------------------------------------------------------
// Problem constants
// ---------------------------------------------------------------------------
#define N_ROWS 131072
#define D 64
#define K 512
#define TILE_M 128
#define NTILES (N_ROWS / TILE_M)    // 1024
#define PADB 144                    // fp16 tile row stride in BYTES (64*2 + 16)
#define MAXCTA 256
#define THREADS 512

// Output layout: [xn | xn | proto | cvae | pdl]
#define XN2_OFF   ((long)N_ROWS * D)
#define PROTO_OFF (2L * N_ROWS * D)
#define CVAE_OFF  (PROTO_OFF + (long)N_ROWS * K)
#define PDL_OFF   (CVAE_OFF + 1)

// Shared memory layout (bytes)
#define OFF_AHI   0                  // fp16 [128] rows x PADB (hi only)
#define OFF_WHI   18432              // fp16 [512] rows x PADB (resident)
#define OFF_WLO   92160
#define OFF_B2    165888             // f32 [512]
#define OFF_A2    167936             // f32 [128]
#define OFF_CMIN  168448             // u32 [512]  (persistent across tiles)
#define OFF_RMIN  170496             // u32 [128]  (per tile)
#define OFF_XS    171008             // f32 x staging [128][64] = 32768 (cp.async)
                                     // (reused as f32 red[512] by last CTA)
#define SMEM_TOTAL 203776

// Device scratch (no allocations allowed)
__device__ float        g_row_partial[NTILES];
__device__ unsigned int g_colmin_cta[MAXCTA * K];   // per-CTA col mins (plain stores)
__device__ unsigned int g_done = 0;                 // completion counter (self-resetting)

// ---------------------------------------------------------------------------
// Helpers (sm_80-level PTX only: ldmatrix + mma.sync + cp.async)
// ---------------------------------------------------------------------------
__device__ __forceinline__ uint32_t smem_u32(const void* p) {
    uint32_t a;
    asm("{ .reg .u64 t; cvta.to.shared.u64 t, %1; cvt.u32.u64 %0, t; }" : "=r"(a) : "l"(p));
    return a;
}
__device__ __forceinline__ void ldsm_x4(uint32_t* r, uint32_t addr) {
    asm volatile("ldmatrix.sync.aligned.m8n8.x4.shared.b16 {%0,%1,%2,%3}, [%4];"
                 : "=r"(r[0]), "=r"(r[1]), "=r"(r[2]), "=r"(r[3]) : "r"(addr));
}
__device__ __forceinline__ void mma_f16(float* d, const uint32_t* a, uint32_t b0, uint32_t b1) {
    asm volatile("mma.sync.aligned.m16n8k16.row.col.f32.f16.f16.f32 "
                 "{%0,%1,%2,%3}, {%4,%5,%6,%7}, {%8,%9}, {%0,%1,%2,%3};"
                 : "+f"(d[0]), "+f"(d[1]), "+f"(d[2]), "+f"(d[3])
                 : "r"(a[0]), "r"(a[1]), "r"(a[2]), "r"(a[3]), "r"(b0), "r"(b1));
}
__device__ __forceinline__ void cp_async16(uint32_t saddr, const void* gptr) {
    asm volatile("cp.async.cg.shared.global [%0], [%1], 16;"
                 :: "r"(saddr), "l"(gptr) : "memory");
}
#define CP_COMMIT()   asm volatile("cp.async.commit_group;" ::: "memory")
#define CP_WAIT_ALL() asm volatile("cp.async.wait_all;" ::: "memory")

// ---------------------------------------------------------------------------
// Main: PERSISTENT CTAs, 512 threads, fused finalization (last-CTA pattern).
// ---------------------------------------------------------------------------
__global__ __launch_bounds__(THREADS, 1)
void swav_main_kernel(const float* __restrict__ x, const float* __restrict__ W,
                      const float* __restrict__ recon, const float* __restrict__ kl,
                      const float* __restrict__ mmd,
                      float* __restrict__ out, int nsm) {
    extern __shared__ __align__(16) char sm[];
    float*        b2s    = (float*)(sm + OFF_B2);
    float*        a2s    = (float*)(sm + OFF_A2);
    unsigned int* cmin_s = (unsigned int*)(sm + OFF_CMIN);
    unsigned int* rmin_s = (unsigned int*)(sm + OFF_RMIN);

    const uint32_t sb  = smem_u32(sm);
    const int t   = threadIdx.x;
    const int lid = t & 31;
    const int wid = t >> 5;

    // ---- One-time: W -> fp16 hi/lo smem tiles + b2 (one row per thread) ----
    {
        const int r = t;
        const float4* wr = (const float4*)(W + (long)r * D);
        float b2 = 0.f;
        #pragma unroll
        for (int j = 0; j < 16; ++j) {
            float4 w4 = wr[j];
            b2 = fmaf(w4.x, w4.x, fmaf(w4.y, w4.y,
                 fmaf(w4.z, w4.z, fmaf(w4.w, w4.w, b2))));
            __half hx = __float2half_rn(w4.x), hy = __float2half_rn(w4.y);
            __half hz = __float2half_rn(w4.z), hw = __float2half_rn(w4.w);
            __half2 hp0 = __halves2half2(hx, hy);
            __half2 hp1 = __halves2half2(hz, hw);
            __half2 lp0 = __halves2half2(__float2half_rn(w4.x - __half2float(hx)),
                                         __float2half_rn(w4.y - __half2float(hy)));
            __half2 lp1 = __halves2half2(__float2half_rn(w4.z - __half2float(hz)),
                                         __float2half_rn(w4.w - __half2float(hw)));
            *(uint2*)(sm + OFF_WHI + r * PADB + j * 8) =
                make_uint2(*(unsigned*)&hp0, *(unsigned*)&hp1);
            *(uint2*)(sm + OFF_WLO + r * PADB + j * 8) =
                make_uint2(*(unsigned*)&lp0, *(unsigned*)&lp1);
        }
        b2s[r] = b2;
        cmin_s[r] = 0x7F800000u;
    }

    // Prefetch x for first tile
    {
        int tile0 = blockIdx.x;
        if (tile0 < NTILES) {
            const char* gx = (const char*)(x + (long)tile0 * TILE_M * D);
            #pragma unroll
            for (int i = 0; i < 4; ++i) {
                int idx = t + i * THREADS;
                cp_async16(sb + OFF_XS + idx * 16, gx + (long)idx * 16);
            }
        }
        CP_COMMIT();
    }

    // ldmatrix lane addressing (tile-invariant). 16 warps: wy row group,
    // wx in 0..3 -> 128-col strip; 2 passes of 64 cols inside strip.
    const int wy = wid & 3, wx = wid >> 2;
    const int m0 = wy * 32;
    const uint32_t a_off    = (uint32_t)(m0 + (lid & 15)) * PADB + ((lid >> 4) * 16);
    const uint32_t aaddr_hi = sb + OFF_AHI + a_off;
    const uint32_t b_rowi   = ((lid >> 4) << 3) + (lid & 7);
    const uint32_t b_koff   = ((lid >> 3) & 1) * 16;

    // ================= persistent tile loop =================
    for (int tile = blockIdx.x; tile < NTILES; tile += nsm) {
        const long row0 = (long)tile * TILE_M;

        CP_WAIT_ALL();
        __syncthreads();   // staged x ready; W tiles ready (first iter)

        // ---- read staged x into regs ----
        float4 v[4]; float s[4];
        #pragma unroll
        for (int i = 0; i < 4; ++i) {
            int idx = t + i * THREADS;                // [128 rows][16 float4]
            v[i] = *(const float4*)(sm + OFF_XS + idx * 16);
            s[i] = fmaf(v[i].x, v[i].x, fmaf(v[i].y, v[i].y,
                    fmaf(v[i].z, v[i].z, v[i].w * v[i].w)));
        }
        __syncthreads();   // staging consumed -> safe to overwrite

        // ---- prefetch next tile's x (overlaps with pack + GEMM) ----
        {
            int nxt = tile + nsm;
            if (nxt < NTILES) {
                const char* gx = (const char*)(x + (long)nxt * TILE_M * D);
                #pragma unroll
                for (int i = 0; i < 4; ++i) {
                    int idx = t + i * THREADS;
                    cp_async16(sb + OFF_XS + idx * 16, gx + (long)idx * 16);
                }
            }
            CP_COMMIT();
        }

        // ---- normalize (16 lanes per row), write xn x2, build A hi tile ----
        #pragma unroll
        for (int m = 1; m < 16; m <<= 1)
            #pragma unroll
            for (int i = 0; i < 4; ++i)
                s[i] += __shfl_xor_sync(0xffffffffu, s[i], m);
        {
            float4* xn1 = (float4*)(out + row0 * D);
            float4* xn2 = (float4*)(out + XN2_OFF + row0 * D);
            #pragma unroll
            for (int i = 0; i < 4; ++i) {
                int idx = t + i * THREADS;
                int r = idx >> 4, c = idx & 15;
                float inv = 1.0f / fmaxf(sqrtf(s[i]), 1e-12f);
                float4 w4 = make_float4(v[i].x * inv, v[i].y * inv,
                                        v[i].z * inv, v[i].w * inv);
                xn1[idx] = w4;
                xn2[idx] = w4;
                if ((t & 15) == 0) a2s[r] = s[i] * inv * inv;

                __half2 hp0 = __floats2half2_rn(w4.x, w4.y);
                __half2 hp1 = __floats2half2_rn(w4.z, w4.w);
                *(uint2*)(sm + OFF_AHI + r * PADB + c * 8) =
                    make_uint2(*(unsigned*)&hp0, *(unsigned*)&hp1);
            }
        }
        if (t < TILE_M) rmin_s[t] = 0x7F800000u;
        __syncthreads();

        // ---- 2-product HMMA GEMM + epilogue, 2 passes of 64 cols ----
        float a2r[2][2];
        #pragma unroll
        for (int mf = 0; mf < 2; ++mf) {
            a2r[mf][0] = a2s[m0 + mf * 16 + (lid >> 2)];
            a2r[mf][1] = a2s[m0 + mf * 16 + (lid >> 2) + 8];
        }
        float rowmin[4];
        #pragma unroll
        for (int j = 0; j < 4; ++j) rowmin[j] = 3.0e38f;

        #pragma unroll 1
        for (int h = 0; h < 2; ++h) {
            const int nb = wx * 128 + h * 64;
            float acc[2][8][4];
            #pragma unroll
            for (int mf = 0; mf < 2; ++mf)
                #pragma unroll
                for (int p = 0; p < 8; ++p)
                    #pragma unroll
                    for (int q = 0; q < 4; ++q) acc[mf][p][q] = 0.f;

            #pragma unroll 1
            for (int k = 0; k < 4; ++k) {
                const uint32_t ka = (uint32_t)k * 32;
                uint32_t ah[2][4];
                ldsm_x4(ah[0], aaddr_hi + ka);
                ldsm_x4(ah[1], aaddr_hi + 16 * PADB + ka);
                // B-fragment prefetch pipeline: load pg+1 before pg's MMAs.
                uint32_t bh[4], bl[4];
                {
                    uint32_t b0 = sb + OFF_WHI +
                        (uint32_t)(nb + b_rowi) * PADB + b_koff + ka;
                    ldsm_x4(bh, b0);
                    ldsm_x4(bl, b0 + (OFF_WLO - OFF_WHI));
                }
                #pragma unroll
                for (int pg = 0; pg < 4; ++pg) {     // 16-col groups
                    uint32_t nh[4], nl[4];
                    if (pg < 3) {
                        uint32_t bn = sb + OFF_WHI +
                            (uint32_t)(nb + (pg + 1) * 16 + b_rowi) * PADB + b_koff + ka;
                        ldsm_x4(nh, bn);
                        ldsm_x4(nl, bn + (OFF_WLO - OFF_WHI));
                    }
                    // Product-major interleave: 4 independent accumulator chains
                    mma_f16(acc[0][2 * pg],     ah[0], bh[0], bh[1]);   // hh
                    mma_f16(acc[0][2 * pg + 1], ah[0], bh[2], bh[3]);
                    mma_f16(acc[1][2 * pg],     ah[1], bh[0], bh[1]);
                    mma_f16(acc[1][2 * pg + 1], ah[1], bh[2], bh[3]);
                    mma_f16(acc[0][2 * pg],     ah[0], bl[0], bl[1]);   // hl
                    mma_f16(acc[0][2 * pg + 1], ah[0], bl[2], bl[3]);
                    mma_f16(acc[1][2 * pg],     ah[1], bl[0], bl[1]);
                    mma_f16(acc[1][2 * pg + 1], ah[1], bl[2], bl[3]);
                    #pragma unroll
                    for (int q = 0; q < 4; ++q) { bh[q] = nh[q]; bl[q] = nl[q]; }
                }
            }

            // Epilogue: streaming proto stores + z-mins, from registers
            #pragma unroll
            for (int p = 0; p < 8; ++p) {
                const int c = nb + p * 8 + 2 * (lid & 3);
                const float b2c0 = b2s[c], b2c1 = b2s[c + 1];
                float cm0 = 3.0e38f, cm1 = 3.0e38f;
                #pragma unroll
                for (int mf = 0; mf < 2; ++mf) {
                    float* d = acc[mf][p];
                    const int r0 = m0 + mf * 16 + (lid >> 2);
                    __stcs((float2*)(out + PROTO_OFF + (row0 + r0) * (long)K + c),
                           make_float2(d[0], d[1]));
                    __stcs((float2*)(out + PROTO_OFF + (row0 + r0 + 8) * (long)K + c),
                           make_float2(d[2], d[3]));
                    float z0 = fmaxf(fmaf(-2.f, d[0], a2r[mf][0] + b2c0), 0.f);
                    float z1 = fmaxf(fmaf(-2.f, d[1], a2r[mf][0] + b2c1), 0.f);
                    float z2 = fmaxf(fmaf(-2.f, d[2], a2r[mf][1] + b2c0), 0.f);
                    float z3 = fmaxf(fmaf(-2.f, d[3], a2r[mf][1] + b2c1), 0.f);
                    rowmin[mf * 2]     = fminf(rowmin[mf * 2],     fminf(z0, z1));
                    rowmin[mf * 2 + 1] = fminf(rowmin[mf * 2 + 1], fminf(z2, z3));
                    cm0 = fminf(cm0, fminf(z0, z2));
                    cm1 = fminf(cm1, fminf(z1, z3));
                }
                #pragma unroll
                for (int o = 4; o < 32; o <<= 1) {
                    cm0 = fminf(cm0, __shfl_xor_sync(0xffffffffu, cm0, o));
                    cm1 = fminf(cm1, __shfl_xor_sync(0xffffffffu, cm1, o));
                }
                if (lid < 4) {
                    atomicMin(&cmin_s[c],     __float_as_uint(cm0));
                    atomicMin(&cmin_s[c + 1], __float_as_uint(cm1));
                }
            }
        }

        // Row-min: quad reduce then smem atomics
        #pragma unroll
        for (int o = 1; o < 4; o <<= 1)
            #pragma unroll
            for (int j = 0; j < 4; ++j)
                rowmin[j] = fminf(rowmin[j], __shfl_xor_sync(0xffffffffu, rowmin[j], o));
        if ((lid & 3) == 0) {
            const int rq = lid >> 2;
            atomicMin(&rmin_s[m0 + rq],      __float_as_uint(rowmin[0]));
            atomicMin(&rmin_s[m0 + rq + 8],  __float_as_uint(rowmin[1]));
            atomicMin(&rmin_s[m0 + 16 + rq], __float_as_uint(rowmin[2]));
            atomicMin(&rmin_s[m0 + 24 + rq], __float_as_uint(rowmin[3]));
        }
        __syncthreads();

        // Per-tile row reduction: single warp, shuffle tree
        if (wid == 0) {
            float rs = 0.f;
            #pragma unroll
            for (int i = 0; i < 4; ++i)
                rs += sqrtf(fmaxf(__uint_as_float(rmin_s[lid * 4 + i]), 1e-12f));
            #pragma unroll
            for (int o = 16; o > 0; o >>= 1)
                rs += __shfl_xor_sync(0xffffffffu, rs, o);
            if (lid == 0) g_row_partial[tile] = rs;
        }
    }

    // ---- per-CTA column mins -> plain global stores ----
    g_colmin_cta[blockIdx.x * K + t] = cmin_s[t];

    // ---- fused finalization: last CTA to arrive reduces everything ----
    __threadfence();           // publish g_row_partial + g_colmin_cta
    __syncthreads();           // all threads' stores precede the arrival
    __shared__ unsigned int s_last;
    if (t == 0) {
        // atomicInc wraps to 0 at nsm-1 -> self-resetting across graph replays
        unsigned int old = atomicInc(&g_done, (unsigned)(nsm - 1));
        s_last = (old == (unsigned)(nsm - 1)) ? 1u : 0u;
    }
    __syncthreads();
    if (s_last) {
        float* red = (float*)(sm + OFF_XS);   // reuse staging as red[512]

        // rowsum over 1024 tiles (L2-hot)
        float rs = g_row_partial[t] + g_row_partial[t + 512];
        red[t] = rs;
        __syncthreads();
        for (int st = 256; st > 0; st >>= 1) {
            if (t < st) red[t] += red[t + st];
            __syncthreads();
        }
        float rowsum = red[0];
        __syncthreads();

        // colmin over nsm CTAs, 8 independent chains (L2-hot)
        unsigned int m[8];
        #pragma unroll
        for (int j = 0; j < 8; ++j) m[j] = 0x7F800000u;
        int i = 0;
        for (; i + 8 <= nsm; i += 8) {
            #pragma unroll
            for (int j = 0; j < 8; ++j)
                m[j] = min(m[j], g_colmin_cta[(i + j) * K + t]);
        }
        for (; i < nsm; ++i) m[0] = min(m[0], g_colmin_cta[i * K + t]);
        #pragma unroll
        for (int j = 1; j < 8; ++j) m[0] = min(m[0], m[j]);

        red[t] = sqrtf(fmaxf(__uint_as_float(m[0]), 1e-12f));
        __syncthreads();
        for (int st = 256; st > 0; st >>= 1) {
            if (t < st) red[t] += red[t + st];
            __syncthreads();
        }

        if (t == 0) {
            float pdl = 0.5f * (rowsum / (float)N_ROWS) + 0.5f * (red[0] / (float)K);
            out[CVAE_OFF] = recon[0] + 0.5f * kl[0] + mmd[0];
            out[PDL_OFF]  = pdl;
        }
    }
}

// ---------------------------------------------------------------------------
extern "C" void kernel_launch(void* const* d_in, const int* in_sizes, int n_in,
                              void* d_out, int out_size) {
    const float* x     = (const float*)d_in[0];
    const float* W     = (const float*)d_in[1];
    const float* recon = (const float*)d_in[2];
    const float* kl    = (const float*)d_in[3];
    const float* mmd   = (const float*)d_in[4];
    float* out = (float*)d_out;

    static int nsm = 0;
    if (nsm == 0) {
        cudaDeviceGetAttribute(&nsm, cudaDevAttrMultiProcessorCount, 0);
        if (nsm <= 0) nsm = 148;
        if (nsm > MAXCTA) nsm = MAXCTA;
        cudaFuncSetAttribute(swav_main_kernel,
                             cudaFuncAttributeMaxDynamicSharedMemorySize, SMEM_TOTAL);
    }

    swav_main_kernel<<<nsm, THREADS, SMEM_TOTAL>>>(x, W, recon, kl, mmd, out, nsm);
}

// round 16
// speedup vs baseline: 1.1026x; 1.0588x over previous
#include <cuda_runtime.h>
#include <cuda_fp16.h>
#include <math.h>
#include <stdint.h>

// ---------------------------------------------------------------------------
// Problem constants
// ---------------------------------------------------------------------------
#define N_ROWS 131072
#define D 64
#define K 512
#define TILE_M 128
#define NTILES (N_ROWS / TILE_M)    // 1024
#define PADB 144                    // fp16 tile row stride in BYTES (64*2 + 16)
#define MAXCTA 256
#define THREADS 512

// Output layout: [xn | xn | proto | cvae | pdl]
#define XN2_OFF   ((long)N_ROWS * D)
#define PROTO_OFF (2L * N_ROWS * D)
#define CVAE_OFF  (PROTO_OFF + (long)N_ROWS * K)
#define PDL_OFF   (CVAE_OFF + 1)

// Shared memory layout (bytes)
#define OFF_AHI   0                  // fp16 [128] rows x PADB (hi only)
#define OFF_WHI   18432              // fp16 [512] rows x PADB (resident)
#define OFF_WLO   92160
#define OFF_B2    165888             // f32 [512]
#define OFF_A2    167936             // f32 [128]
#define OFF_CMIN  168448             // u32 [512]  (persistent across tiles)
#define OFF_RMIN  170496             // u32 [128]  (per tile)
#define OFF_XS    171008             // f32 x staging [128][64] = 32768 (cp.async)
                                     // (reused as f32 red[512] by last CTA)
#define SMEM_TOTAL 203776

// Device scratch (no allocations allowed)
__device__ float        g_row_partial[NTILES];
__device__ unsigned int g_colmin_cta[MAXCTA * K];   // per-CTA col mins (plain stores)
__device__ unsigned int g_done = 0;                 // completion counter (self-resetting)

// ---------------------------------------------------------------------------
// Helpers (sm_80-level PTX only: ldmatrix + mma.sync + cp.async)
// ---------------------------------------------------------------------------
__device__ __forceinline__ uint32_t smem_u32(const void* p) {
    uint32_t a;
    asm("{ .reg .u64 t; cvta.to.shared.u64 t, %1; cvt.u32.u64 %0, t; }" : "=r"(a) : "l"(p));
    return a;
}
__device__ __forceinline__ void ldsm_x4(uint32_t* r, uint32_t addr) {
    asm volatile("ldmatrix.sync.aligned.m8n8.x4.shared.b16 {%0,%1,%2,%3}, [%4];"
                 : "=r"(r[0]), "=r"(r[1]), "=r"(r[2]), "=r"(r[3]) : "r"(addr));
}
__device__ __forceinline__ void mma_f16(float* d, const uint32_t* a, uint32_t b0, uint32_t b1) {
    asm volatile("mma.sync.aligned.m16n8k16.row.col.f32.f16.f16.f32 "
                 "{%0,%1,%2,%3}, {%4,%5,%6,%7}, {%8,%9}, {%0,%1,%2,%3};"
                 : "+f"(d[0]), "+f"(d[1]), "+f"(d[2]), "+f"(d[3])
                 : "r"(a[0]), "r"(a[1]), "r"(a[2]), "r"(a[3]), "r"(b0), "r"(b1));
}
__device__ __forceinline__ void cp_async16(uint32_t saddr, const void* gptr) {
    asm volatile("cp.async.cg.shared.global [%0], [%1], 16;"
                 :: "r"(saddr), "l"(gptr) : "memory");
}
#define CP_COMMIT()   asm volatile("cp.async.commit_group;" ::: "memory")
#define CP_WAIT_ALL() asm volatile("cp.async.wait_all;" ::: "memory")

// ---------------------------------------------------------------------------
// Main: PERSISTENT CTAs, 512 threads, fused finalization. Warp tile 64x64
// (wy 0..1, wx 0..7; 2 passes of 32 cols) -> B ldsm redundancy 4x -> 2x.
// ---------------------------------------------------------------------------
__global__ __launch_bounds__(THREADS, 1)
void swav_main_kernel(const float* __restrict__ x, const float* __restrict__ W,
                      const float* __restrict__ recon, const float* __restrict__ kl,
                      const float* __restrict__ mmd,
                      float* __restrict__ out, int nsm) {
    extern __shared__ __align__(16) char sm[];
    float*        b2s    = (float*)(sm + OFF_B2);
    float*        a2s    = (float*)(sm + OFF_A2);
    unsigned int* cmin_s = (unsigned int*)(sm + OFF_CMIN);
    unsigned int* rmin_s = (unsigned int*)(sm + OFF_RMIN);

    const uint32_t sb  = smem_u32(sm);
    const int t   = threadIdx.x;
    const int lid = t & 31;
    const int wid = t >> 5;

    // ---- One-time: W -> fp16 hi/lo smem tiles + b2 (one row per thread) ----
    {
        const int r = t;
        const float4* wr = (const float4*)(W + (long)r * D);
        float b2 = 0.f;
        #pragma unroll
        for (int j = 0; j < 16; ++j) {
            float4 w4 = wr[j];
            b2 = fmaf(w4.x, w4.x, fmaf(w4.y, w4.y,
                 fmaf(w4.z, w4.z, fmaf(w4.w, w4.w, b2))));
            __half hx = __float2half_rn(w4.x), hy = __float2half_rn(w4.y);
            __half hz = __float2half_rn(w4.z), hw = __float2half_rn(w4.w);
            __half2 hp0 = __halves2half2(hx, hy);
            __half2 hp1 = __halves2half2(hz, hw);
            __half2 lp0 = __halves2half2(__float2half_rn(w4.x - __half2float(hx)),
                                         __float2half_rn(w4.y - __half2float(hy)));
            __half2 lp1 = __halves2half2(__float2half_rn(w4.z - __half2float(hz)),
                                         __float2half_rn(w4.w - __half2float(hw)));
            *(uint2*)(sm + OFF_WHI + r * PADB + j * 8) =
                make_uint2(*(unsigned*)&hp0, *(unsigned*)&hp1);
            *(uint2*)(sm + OFF_WLO + r * PADB + j * 8) =
                make_uint2(*(unsigned*)&lp0, *(unsigned*)&lp1);
        }
        b2s[r] = b2;
        cmin_s[r] = 0x7F800000u;
    }

    // Prefetch x for first tile
    {
        int tile0 = blockIdx.x;
        if (tile0 < NTILES) {
            const char* gx = (const char*)(x + (long)tile0 * TILE_M * D);
            #pragma unroll
            for (int i = 0; i < 4; ++i) {
                int idx = t + i * THREADS;
                cp_async16(sb + OFF_XS + idx * 16, gx + (long)idx * 16);
            }
        }
        CP_COMMIT();
    }

    // ldmatrix lane addressing (tile-invariant). 16 warps: wy in 0..1 (64-row
    // group), wx in 0..7 (64-col strip); 2 passes of 32 cols inside strip.
    const int wy = wid & 1, wx = wid >> 1;
    const int m0 = wy * 64;
    const uint32_t a_off    = (uint32_t)(m0 + (lid & 15)) * PADB + ((lid >> 4) * 16);
    const uint32_t aaddr_hi = sb + OFF_AHI + a_off;
    const uint32_t b_rowi   = ((lid >> 4) << 3) + (lid & 7);
    const uint32_t b_koff   = ((lid >> 3) & 1) * 16;

    // ================= persistent tile loop =================
    for (int tile = blockIdx.x; tile < NTILES; tile += nsm) {
        const long row0 = (long)tile * TILE_M;

        CP_WAIT_ALL();
        __syncthreads();   // staged x ready; W tiles ready (first iter)

        // ---- read staged x into regs ----
        float4 v[4]; float s[4];
        #pragma unroll
        for (int i = 0; i < 4; ++i) {
            int idx = t + i * THREADS;                // [128 rows][16 float4]
            v[i] = *(const float4*)(sm + OFF_XS + idx * 16);
            s[i] = fmaf(v[i].x, v[i].x, fmaf(v[i].y, v[i].y,
                    fmaf(v[i].z, v[i].z, v[i].w * v[i].w)));
        }
        __syncthreads();   // staging consumed -> safe to overwrite

        // ---- prefetch next tile's x (overlaps with pack + GEMM) ----
        {
            int nxt = tile + nsm;
            if (nxt < NTILES) {
                const char* gx = (const char*)(x + (long)nxt * TILE_M * D);
                #pragma unroll
                for (int i = 0; i < 4; ++i) {
                    int idx = t + i * THREADS;
                    cp_async16(sb + OFF_XS + idx * 16, gx + (long)idx * 16);
                }
            }
            CP_COMMIT();
        }

        // ---- normalize (16 lanes per row), write xn x2, build A hi tile ----
        #pragma unroll
        for (int m = 1; m < 16; m <<= 1)
            #pragma unroll
            for (int i = 0; i < 4; ++i)
                s[i] += __shfl_xor_sync(0xffffffffu, s[i], m);
        {
            float4* xn1 = (float4*)(out + row0 * D);
            float4* xn2 = (float4*)(out + XN2_OFF + row0 * D);
            #pragma unroll
            for (int i = 0; i < 4; ++i) {
                int idx = t + i * THREADS;
                int r = idx >> 4, c = idx & 15;
                float inv = 1.0f / fmaxf(sqrtf(s[i]), 1e-12f);
                float4 w4 = make_float4(v[i].x * inv, v[i].y * inv,
                                        v[i].z * inv, v[i].w * inv);
                xn1[idx] = w4;
                xn2[idx] = w4;
                if ((t & 15) == 0) a2s[r] = s[i] * inv * inv;

                __half2 hp0 = __floats2half2_rn(w4.x, w4.y);
                __half2 hp1 = __floats2half2_rn(w4.z, w4.w);
                *(uint2*)(sm + OFF_AHI + r * PADB + c * 8) =
                    make_uint2(*(unsigned*)&hp0, *(unsigned*)&hp1);
            }
        }
        if (t < TILE_M) rmin_s[t] = 0x7F800000u;
        __syncthreads();

        // ---- 2-product HMMA GEMM + epilogue, 2 passes of 32 cols ----
        float a2r[4][2];
        #pragma unroll
        for (int mf = 0; mf < 4; ++mf) {
            a2r[mf][0] = a2s[m0 + mf * 16 + (lid >> 2)];
            a2r[mf][1] = a2s[m0 + mf * 16 + (lid >> 2) + 8];
        }
        float rowmin[8];
        #pragma unroll
        for (int j = 0; j < 8; ++j) rowmin[j] = 3.0e38f;

        #pragma unroll 1
        for (int h = 0; h < 2; ++h) {
            const int nb = wx * 64 + h * 32;
            float acc[4][4][4];
            #pragma unroll
            for (int mf = 0; mf < 4; ++mf)
                #pragma unroll
                for (int p = 0; p < 4; ++p)
                    #pragma unroll
                    for (int q = 0; q < 4; ++q) acc[mf][p][q] = 0.f;

            #pragma unroll 1
            for (int k = 0; k < 4; ++k) {
                const uint32_t ka = (uint32_t)k * 32;
                uint32_t ah[4][4];
                ldsm_x4(ah[0], aaddr_hi + ka);
                ldsm_x4(ah[1], aaddr_hi + 16 * PADB + ka);
                ldsm_x4(ah[2], aaddr_hi + 32 * PADB + ka);
                ldsm_x4(ah[3], aaddr_hi + 48 * PADB + ka);
                // B-fragment prefetch: pg0 loaded here, pg1 during pg0 MMAs.
                uint32_t bh[4], bl[4];
                {
                    uint32_t b0 = sb + OFF_WHI +
                        (uint32_t)(nb + b_rowi) * PADB + b_koff + ka;
                    ldsm_x4(bh, b0);
                    ldsm_x4(bl, b0 + (OFF_WLO - OFF_WHI));
                }
                #pragma unroll
                for (int pg = 0; pg < 2; ++pg) {     // 16-col groups
                    uint32_t nh[4], nl[4];
                    if (pg < 1) {
                        uint32_t bn = sb + OFF_WHI +
                            (uint32_t)(nb + 16 + b_rowi) * PADB + b_koff + ka;
                        ldsm_x4(nh, bn);
                        ldsm_x4(nl, bn + (OFF_WLO - OFF_WHI));
                    }
                    // Product-major interleave: 8 independent acc chains (hh),
                    // then the dependent hl set 8 issue slots later.
                    mma_f16(acc[0][2 * pg],     ah[0], bh[0], bh[1]);   // hh
                    mma_f16(acc[0][2 * pg + 1], ah[0], bh[2], bh[3]);
                    mma_f16(acc[1][2 * pg],     ah[1], bh[0], bh[1]);
                    mma_f16(acc[1][2 * pg + 1], ah[1], bh[2], bh[3]);
                    mma_f16(acc[2][2 * pg],     ah[2], bh[0], bh[1]);
                    mma_f16(acc[2][2 * pg + 1], ah[2], bh[2], bh[3]);
                    mma_f16(acc[3][2 * pg],     ah[3], bh[0], bh[1]);
                    mma_f16(acc[3][2 * pg + 1], ah[3], bh[2], bh[3]);
                    mma_f16(acc[0][2 * pg],     ah[0], bl[0], bl[1]);   // hl
                    mma_f16(acc[0][2 * pg + 1], ah[0], bl[2], bl[3]);
                    mma_f16(acc[1][2 * pg],     ah[1], bl[0], bl[1]);
                    mma_f16(acc[1][2 * pg + 1], ah[1], bl[2], bl[3]);
                    mma_f16(acc[2][2 * pg],     ah[2], bl[0], bl[1]);
                    mma_f16(acc[2][2 * pg + 1], ah[2], bl[2], bl[3]);
                    mma_f16(acc[3][2 * pg],     ah[3], bl[0], bl[1]);
                    mma_f16(acc[3][2 * pg + 1], ah[3], bl[2], bl[3]);
                    #pragma unroll
                    for (int q = 0; q < 4; ++q) { bh[q] = nh[q]; bl[q] = nl[q]; }
                }
            }

            // Epilogue: streaming proto stores + z-mins, from registers
            #pragma unroll
            for (int p = 0; p < 4; ++p) {
                const int c = nb + p * 8 + 2 * (lid & 3);
                const float b2c0 = b2s[c], b2c1 = b2s[c + 1];
                float cm0 = 3.0e38f, cm1 = 3.0e38f;
                #pragma unroll
                for (int mf = 0; mf < 4; ++mf) {
                    float* d = acc[mf][p];
                    const int r0 = m0 + mf * 16 + (lid >> 2);
                    __stcs((float2*)(out + PROTO_OFF + (row0 + r0) * (long)K + c),
                           make_float2(d[0], d[1]));
                    __stcs((float2*)(out + PROTO_OFF + (row0 + r0 + 8) * (long)K + c),
                           make_float2(d[2], d[3]));
                    float z0 = fmaxf(fmaf(-2.f, d[0], a2r[mf][0] + b2c0), 0.f);
                    float z1 = fmaxf(fmaf(-2.f, d[1], a2r[mf][0] + b2c1), 0.f);
                    float z2 = fmaxf(fmaf(-2.f, d[2], a2r[mf][1] + b2c0), 0.f);
                    float z3 = fmaxf(fmaf(-2.f, d[3], a2r[mf][1] + b2c1), 0.f);
                    rowmin[mf * 2]     = fminf(rowmin[mf * 2],     fminf(z0, z1));
                    rowmin[mf * 2 + 1] = fminf(rowmin[mf * 2 + 1], fminf(z2, z3));
                    cm0 = fminf(cm0, fminf(z0, z2));
                    cm1 = fminf(cm1, fminf(z1, z3));
                }
                #pragma unroll
                for (int o = 4; o < 32; o <<= 1) {
                    cm0 = fminf(cm0, __shfl_xor_sync(0xffffffffu, cm0, o));
                    cm1 = fminf(cm1, __shfl_xor_sync(0xffffffffu, cm1, o));
                }
                if (lid < 4) {
                    atomicMin(&cmin_s[c],     __float_as_uint(cm0));
                    atomicMin(&cmin_s[c + 1], __float_as_uint(cm1));
                }
            }
        }

        // Row-min: quad reduce then smem atomics (8 row groups per lane)
        #pragma unroll
        for (int o = 1; o < 4; o <<= 1)
            #pragma unroll
            for (int j = 0; j < 8; ++j)
                rowmin[j] = fminf(rowmin[j], __shfl_xor_sync(0xffffffffu, rowmin[j], o));
        if ((lid & 3) == 0) {
            const int rq = lid >> 2;
            #pragma unroll
            for (int mf = 0; mf < 4; ++mf) {
                atomicMin(&rmin_s[m0 + mf * 16 + rq],     __float_as_uint(rowmin[mf * 2]));
                atomicMin(&rmin_s[m0 + mf * 16 + rq + 8], __float_as_uint(rowmin[mf * 2 + 1]));
            }
        }
        __syncthreads();

        // Per-tile row reduction: single warp, shuffle tree
        if (wid == 0) {
            float rs = 0.f;
            #pragma unroll
            for (int i = 0; i < 4; ++i)
                rs += sqrtf(fmaxf(__uint_as_float(rmin_s[lid * 4 + i]), 1e-12f));
            #pragma unroll
            for (int o = 16; o > 0; o >>= 1)
                rs += __shfl_xor_sync(0xffffffffu, rs, o);
            if (lid == 0) g_row_partial[tile] = rs;
        }
    }

    // ---- per-CTA column mins -> plain global stores ----
    g_colmin_cta[blockIdx.x * K + t] = cmin_s[t];

    // ---- fused finalization: last CTA to arrive reduces everything ----
    __threadfence();           // publish g_row_partial + g_colmin_cta
    __syncthreads();           // all threads' stores precede the arrival
    __shared__ unsigned int s_last;
    if (t == 0) {
        // atomicInc wraps to 0 at nsm-1 -> self-resetting across graph replays
        unsigned int old = atomicInc(&g_done, (unsigned)(nsm - 1));
        s_last = (old == (unsigned)(nsm - 1)) ? 1u : 0u;
    }
    __syncthreads();
    if (s_last) {
        float* red = (float*)(sm + OFF_XS);   // reuse staging as red[512]

        // rowsum over 1024 tiles (L2-hot)
        float rs = g_row_partial[t] + g_row_partial[t + 512];
        red[t] = rs;
        __syncthreads();
        for (int st = 256; st > 0; st >>= 1) {
            if (t < st) red[t] += red[t + st];
            __syncthreads();
        }
        float rowsum = red[0];
        __syncthreads();

        // colmin over nsm CTAs, 8 independent chains (L2-hot)
        unsigned int m[8];
        #pragma unroll
        for (int j = 0; j < 8; ++j) m[j] = 0x7F800000u;
        int i = 0;
        for (; i + 8 <= nsm; i += 8) {
            #pragma unroll
            for (int j = 0; j < 8; ++j)
                m[j] = min(m[j], g_colmin_cta[(i + j) * K + t]);
        }
        for (; i < nsm; ++i) m[0] = min(m[0], g_colmin_cta[i * K + t]);
        #pragma unroll
        for (int j = 1; j < 8; ++j) m[0] = min(m[0], m[j]);

        red[t] = sqrtf(fmaxf(__uint_as_float(m[0]), 1e-12f));
        __syncthreads();
        for (int st = 256; st > 0; st >>= 1) {
            if (t < st) red[t] += red[t + st];
            __syncthreads();
        }

        if (t == 0) {
            float pdl = 0.5f * (rowsum / (float)N_ROWS) + 0.5f * (red[0] / (float)K);
            out[CVAE_OFF] = recon[0] + 0.5f * kl[0] + mmd[0];
            out[PDL_OFF]  = pdl;
        }
    }
}

// ---------------------------------------------------------------------------
extern "C" void kernel_launch(void* const* d_in, const int* in_sizes, int n_in,
                              void* d_out, int out_size) {
    const float* x     = (const float*)d_in[0];
    const float* W     = (const float*)d_in[1];
    const float* recon = (const float*)d_in[2];
    const float* kl    = (const float*)d_in[3];
    const float* mmd   = (const float*)d_in[4];
    float* out = (float*)d_out;

    static int nsm = 0;
    if (nsm == 0) {
        cudaDeviceGetAttribute(&nsm, cudaDevAttrMultiProcessorCount, 0);
        if (nsm <= 0) nsm = 148;
        if (nsm > MAXCTA) nsm = MAXCTA;
        cudaFuncSetAttribute(swav_main_kernel,
                             cudaFuncAttributeMaxDynamicSharedMemorySize, SMEM_TOTAL);
    }

    swav_main_kernel<<<nsm, THREADS, SMEM_TOTAL>>>(x, W, recon, kl, mmd, out, nsm);
}

// round 17
// speedup vs baseline: 1.2811x; 1.1619x over previous
#include <cuda_runtime.h>
#include <cuda_fp16.h>
#include <math.h>
#include <stdint.h>

// ---------------------------------------------------------------------------
// Problem constants
// ---------------------------------------------------------------------------
#define N_ROWS 131072
#define D 64
#define K 512
#define TILE_M 128
#define NTILES (N_ROWS / TILE_M)    // 1024
#define PADB 144                    // fp16 tile row stride in BYTES (64*2 + 16)
#define MAXCTA 256
#define THREADS 512

// Output layout: [xn | xn | proto | cvae | pdl]
#define XN2_OFF   ((long)N_ROWS * D)
#define PROTO_OFF (2L * N_ROWS * D)
#define CVAE_OFF  (PROTO_OFF + (long)N_ROWS * K)
#define PDL_OFF   (CVAE_OFF + 1)

// Shared memory layout (bytes)
#define OFF_AHI   0                  // fp16 [128] rows x PADB
#define OFF_WHI   18432              // fp16 [512] rows x PADB (resident)
#define OFF_B2    92160              // f32 [512]
#define OFF_A2    94208              // f32 [128]
#define OFF_CMIN  94720              // u32 [512]  (persistent across tiles)
#define OFF_RMIN  96768              // u32 [128]  (per tile)
#define OFF_XS    97280              // f32 x staging [128][64] = 32768 (cp.async)
                                     // (reused as f32 red[512] by last CTA)
#define SMEM_TOTAL 130048

// Device scratch (no allocations allowed)
__device__ float        g_row_partial[NTILES];
__device__ unsigned int g_colmin_cta[MAXCTA * K];   // per-CTA col mins (plain stores)
__device__ unsigned int g_done = 0;                 // completion counter (self-resetting)

// ---------------------------------------------------------------------------
// Helpers (sm_80-level PTX only: ldmatrix + mma.sync + cp.async)
// ---------------------------------------------------------------------------
__device__ __forceinline__ uint32_t smem_u32(const void* p) {
    uint32_t a;
    asm("{ .reg .u64 t; cvta.to.shared.u64 t, %1; cvt.u32.u64 %0, t; }" : "=r"(a) : "l"(p));
    return a;
}
__device__ __forceinline__ void ldsm_x4(uint32_t* r, uint32_t addr) {
    asm volatile("ldmatrix.sync.aligned.m8n8.x4.shared.b16 {%0,%1,%2,%3}, [%4];"
                 : "=r"(r[0]), "=r"(r[1]), "=r"(r[2]), "=r"(r[3]) : "r"(addr));
}
__device__ __forceinline__ void mma_f16(float* d, const uint32_t* a, uint32_t b0, uint32_t b1) {
    asm volatile("mma.sync.aligned.m16n8k16.row.col.f32.f16.f16.f32 "
                 "{%0,%1,%2,%3}, {%4,%5,%6,%7}, {%8,%9}, {%0,%1,%2,%3};"
                 : "+f"(d[0]), "+f"(d[1]), "+f"(d[2]), "+f"(d[3])
                 : "r"(a[0]), "r"(a[1]), "r"(a[2]), "r"(a[3]), "r"(b0), "r"(b1));
}
__device__ __forceinline__ void cp_async16(uint32_t saddr, const void* gptr) {
    asm volatile("cp.async.cg.shared.global [%0], [%1], 16;"
                 :: "r"(saddr), "l"(gptr) : "memory");
}
#define CP_COMMIT()   asm volatile("cp.async.commit_group;" ::: "memory")
#define CP_WAIT_ALL() asm volatile("cp.async.wait_all;" ::: "memory")

// ---------------------------------------------------------------------------
// Main: PERSISTENT CTAs, 512 threads, fused finalization. Warp tile 64x64,
// SINGLE fp16 product (hi*hi) -> half the MMAs, B-lo ldsm eliminated.
// ---------------------------------------------------------------------------
__global__ __launch_bounds__(THREADS, 1)
void swav_main_kernel(const float* __restrict__ x, const float* __restrict__ W,
                      const float* __restrict__ recon, const float* __restrict__ kl,
                      const float* __restrict__ mmd,
                      float* __restrict__ out, int nsm) {
    extern __shared__ __align__(16) char sm[];
    float*        b2s    = (float*)(sm + OFF_B2);
    float*        a2s    = (float*)(sm + OFF_A2);
    unsigned int* cmin_s = (unsigned int*)(sm + OFF_CMIN);
    unsigned int* rmin_s = (unsigned int*)(sm + OFF_RMIN);

    const uint32_t sb  = smem_u32(sm);
    const int t   = threadIdx.x;
    const int lid = t & 31;
    const int wid = t >> 5;

    // ---- One-time: W -> fp16 hi smem tile + b2 (one row per thread) ----
    {
        const int r = t;
        const float4* wr = (const float4*)(W + (long)r * D);
        float b2 = 0.f;
        #pragma unroll
        for (int j = 0; j < 16; ++j) {
            float4 w4 = wr[j];
            b2 = fmaf(w4.x, w4.x, fmaf(w4.y, w4.y,
                 fmaf(w4.z, w4.z, fmaf(w4.w, w4.w, b2))));
            __half2 hp0 = __floats2half2_rn(w4.x, w4.y);
            __half2 hp1 = __floats2half2_rn(w4.z, w4.w);
            *(uint2*)(sm + OFF_WHI + r * PADB + j * 8) =
                make_uint2(*(unsigned*)&hp0, *(unsigned*)&hp1);
        }
        b2s[r] = b2;
        cmin_s[r] = 0x7F800000u;
    }

    // Prefetch x for first tile
    {
        int tile0 = blockIdx.x;
        if (tile0 < NTILES) {
            const char* gx = (const char*)(x + (long)tile0 * TILE_M * D);
            #pragma unroll
            for (int i = 0; i < 4; ++i) {
                int idx = t + i * THREADS;
                cp_async16(sb + OFF_XS + idx * 16, gx + (long)idx * 16);
            }
        }
        CP_COMMIT();
    }

    // ldmatrix lane addressing (tile-invariant). 16 warps: wy in 0..1 (64-row
    // group), wx in 0..7 (64-col strip); 2 passes of 32 cols inside strip.
    const int wy = wid & 1, wx = wid >> 1;
    const int m0 = wy * 64;
    const uint32_t a_off    = (uint32_t)(m0 + (lid & 15)) * PADB + ((lid >> 4) * 16);
    const uint32_t aaddr_hi = sb + OFF_AHI + a_off;
    const uint32_t b_rowi   = ((lid >> 4) << 3) + (lid & 7);
    const uint32_t b_koff   = ((lid >> 3) & 1) * 16;

    // ================= persistent tile loop =================
    for (int tile = blockIdx.x; tile < NTILES; tile += nsm) {
        const long row0 = (long)tile * TILE_M;

        CP_WAIT_ALL();
        __syncthreads();   // staged x ready; W tiles ready (first iter)

        // ---- read staged x into regs ----
        float4 v[4]; float s[4];
        #pragma unroll
        for (int i = 0; i < 4; ++i) {
            int idx = t + i * THREADS;                // [128 rows][16 float4]
            v[i] = *(const float4*)(sm + OFF_XS + idx * 16);
            s[i] = fmaf(v[i].x, v[i].x, fmaf(v[i].y, v[i].y,
                    fmaf(v[i].z, v[i].z, v[i].w * v[i].w)));
        }
        __syncthreads();   // staging consumed -> safe to overwrite

        // ---- prefetch next tile's x (overlaps with pack + GEMM) ----
        {
            int nxt = tile + nsm;
            if (nxt < NTILES) {
                const char* gx = (const char*)(x + (long)nxt * TILE_M * D);
                #pragma unroll
                for (int i = 0; i < 4; ++i) {
                    int idx = t + i * THREADS;
                    cp_async16(sb + OFF_XS + idx * 16, gx + (long)idx * 16);
                }
            }
            CP_COMMIT();
        }

        // ---- normalize (16 lanes per row), write xn x2, build A hi tile ----
        #pragma unroll
        for (int m = 1; m < 16; m <<= 1)
            #pragma unroll
            for (int i = 0; i < 4; ++i)
                s[i] += __shfl_xor_sync(0xffffffffu, s[i], m);
        {
            float4* xn1 = (float4*)(out + row0 * D);
            float4* xn2 = (float4*)(out + XN2_OFF + row0 * D);
            #pragma unroll
            for (int i = 0; i < 4; ++i) {
                int idx = t + i * THREADS;
                int r = idx >> 4, c = idx & 15;
                float inv = 1.0f / fmaxf(sqrtf(s[i]), 1e-12f);
                float4 w4 = make_float4(v[i].x * inv, v[i].y * inv,
                                        v[i].z * inv, v[i].w * inv);
                xn1[idx] = w4;
                xn2[idx] = w4;
                if ((t & 15) == 0) a2s[r] = s[i] * inv * inv;

                __half2 hp0 = __floats2half2_rn(w4.x, w4.y);
                __half2 hp1 = __floats2half2_rn(w4.z, w4.w);
                *(uint2*)(sm + OFF_AHI + r * PADB + c * 8) =
                    make_uint2(*(unsigned*)&hp0, *(unsigned*)&hp1);
            }
        }
        if (t < TILE_M) rmin_s[t] = 0x7F800000u;
        __syncthreads();

        // ---- single-product HMMA GEMM + epilogue, 2 passes of 32 cols ----
        float a2r[4][2];
        #pragma unroll
        for (int mf = 0; mf < 4; ++mf) {
            a2r[mf][0] = a2s[m0 + mf * 16 + (lid >> 2)];
            a2r[mf][1] = a2s[m0 + mf * 16 + (lid >> 2) + 8];
        }
        float rowmin[8];
        #pragma unroll
        for (int j = 0; j < 8; ++j) rowmin[j] = 3.0e38f;

        #pragma unroll 1
        for (int h = 0; h < 2; ++h) {
            const int nb = wx * 64 + h * 32;
            float acc[4][4][4];
            #pragma unroll
            for (int mf = 0; mf < 4; ++mf)
                #pragma unroll
                for (int p = 0; p < 4; ++p)
                    #pragma unroll
                    for (int q = 0; q < 4; ++q) acc[mf][p][q] = 0.f;

            #pragma unroll 1
            for (int k = 0; k < 4; ++k) {
                const uint32_t ka = (uint32_t)k * 32;
                uint32_t ah[4][4];
                ldsm_x4(ah[0], aaddr_hi + ka);
                ldsm_x4(ah[1], aaddr_hi + 16 * PADB + ka);
                ldsm_x4(ah[2], aaddr_hi + 32 * PADB + ka);
                ldsm_x4(ah[3], aaddr_hi + 48 * PADB + ka);
                // B-fragment prefetch: pg0 loaded here, pg1 during pg0 MMAs.
                uint32_t bh[4];
                ldsm_x4(bh, sb + OFF_WHI +
                        (uint32_t)(nb + b_rowi) * PADB + b_koff + ka);
                #pragma unroll
                for (int pg = 0; pg < 2; ++pg) {     // 16-col groups
                    uint32_t nh[4];
                    if (pg < 1) {
                        ldsm_x4(nh, sb + OFF_WHI +
                                (uint32_t)(nb + 16 + b_rowi) * PADB + b_koff + ka);
                    }
                    // 8 independent accumulator chains
                    mma_f16(acc[0][2 * pg],     ah[0], bh[0], bh[1]);
                    mma_f16(acc[0][2 * pg + 1], ah[0], bh[2], bh[3]);
                    mma_f16(acc[1][2 * pg],     ah[1], bh[0], bh[1]);
                    mma_f16(acc[1][2 * pg + 1], ah[1], bh[2], bh[3]);
                    mma_f16(acc[2][2 * pg],     ah[2], bh[0], bh[1]);
                    mma_f16(acc[2][2 * pg + 1], ah[2], bh[2], bh[3]);
                    mma_f16(acc[3][2 * pg],     ah[3], bh[0], bh[1]);
                    mma_f16(acc[3][2 * pg + 1], ah[3], bh[2], bh[3]);
                    #pragma unroll
                    for (int q = 0; q < 4; ++q) bh[q] = nh[q];
                }
            }

            // Epilogue: streaming proto stores + z-mins, from registers
            #pragma unroll
            for (int p = 0; p < 4; ++p) {
                const int c = nb + p * 8 + 2 * (lid & 3);
                const float b2c0 = b2s[c], b2c1 = b2s[c + 1];
                float cm0 = 3.0e38f, cm1 = 3.0e38f;
                #pragma unroll
                for (int mf = 0; mf < 4; ++mf) {
                    float* d = acc[mf][p];
                    const int r0 = m0 + mf * 16 + (lid >> 2);
                    __stcs((float2*)(out + PROTO_OFF + (row0 + r0) * (long)K + c),
                           make_float2(d[0], d[1]));
                    __stcs((float2*)(out + PROTO_OFF + (row0 + r0 + 8) * (long)K + c),
                           make_float2(d[2], d[3]));
                    float z0 = fmaxf(fmaf(-2.f, d[0], a2r[mf][0] + b2c0), 0.f);
                    float z1 = fmaxf(fmaf(-2.f, d[1], a2r[mf][0] + b2c1), 0.f);
                    float z2 = fmaxf(fmaf(-2.f, d[2], a2r[mf][1] + b2c0), 0.f);
                    float z3 = fmaxf(fmaf(-2.f, d[3], a2r[mf][1] + b2c1), 0.f);
                    rowmin[mf * 2]     = fminf(rowmin[mf * 2],     fminf(z0, z1));
                    rowmin[mf * 2 + 1] = fminf(rowmin[mf * 2 + 1], fminf(z2, z3));
                    cm0 = fminf(cm0, fminf(z0, z2));
                    cm1 = fminf(cm1, fminf(z1, z3));
                }
                #pragma unroll
                for (int o = 4; o < 32; o <<= 1) {
                    cm0 = fminf(cm0, __shfl_xor_sync(0xffffffffu, cm0, o));
                    cm1 = fminf(cm1, __shfl_xor_sync(0xffffffffu, cm1, o));
                }
                if (lid < 4) {
                    atomicMin(&cmin_s[c],     __float_as_uint(cm0));
                    atomicMin(&cmin_s[c + 1], __float_as_uint(cm1));
                }
            }
        }

        // Row-min: quad reduce then smem atomics (8 row groups per lane)
        #pragma unroll
        for (int o = 1; o < 4; o <<= 1)
            #pragma unroll
            for (int j = 0; j < 8; ++j)
                rowmin[j] = fminf(rowmin[j], __shfl_xor_sync(0xffffffffu, rowmin[j], o));
        if ((lid & 3) == 0) {
            const int rq = lid >> 2;
            #pragma unroll
            for (int mf = 0; mf < 4; ++mf) {
                atomicMin(&rmin_s[m0 + mf * 16 + rq],     __float_as_uint(rowmin[mf * 2]));
                atomicMin(&rmin_s[m0 + mf * 16 + rq + 8], __float_as_uint(rowmin[mf * 2 + 1]));
            }
        }
        __syncthreads();

        // Per-tile row reduction: single warp, shuffle tree
        if (wid == 0) {
            float rs = 0.f;
            #pragma unroll
            for (int i = 0; i < 4; ++i)
                rs += sqrtf(fmaxf(__uint_as_float(rmin_s[lid * 4 + i]), 1e-12f));
            #pragma unroll
            for (int o = 16; o > 0; o >>= 1)
                rs += __shfl_xor_sync(0xffffffffu, rs, o);
            if (lid == 0) g_row_partial[tile] = rs;
        }
    }

    // ---- per-CTA column mins -> plain global stores ----
    g_colmin_cta[blockIdx.x * K + t] = cmin_s[t];

    // ---- fused finalization: last CTA to arrive reduces everything ----
    __threadfence();           // publish g_row_partial + g_colmin_cta
    __syncthreads();           // all threads' stores precede the arrival
    __shared__ unsigned int s_last;
    if (t == 0) {
        // atomicInc wraps to 0 at nsm-1 -> self-resetting across graph replays
        unsigned int old = atomicInc(&g_done, (unsigned)(nsm - 1));
        s_last = (old == (unsigned)(nsm - 1)) ? 1u : 0u;
    }
    __syncthreads();
    if (s_last) {
        float* red = (float*)(sm + OFF_XS);   // reuse staging as red[512]

        // rowsum over 1024 tiles (L2-hot)
        float rs = g_row_partial[t] + g_row_partial[t + 512];
        red[t] = rs;
        __syncthreads();
        for (int st = 256; st > 0; st >>= 1) {
            if (t < st) red[t] += red[t + st];
            __syncthreads();
        }
        float rowsum = red[0];
        __syncthreads();

        // colmin over nsm CTAs, 8 independent chains (L2-hot)
        unsigned int m[8];
        #pragma unroll
        for (int j = 0; j < 8; ++j) m[j] = 0x7F800000u;
        int i = 0;
        for (; i + 8 <= nsm; i += 8) {
            #pragma unroll
            for (int j = 0; j < 8; ++j)
                m[j] = min(m[j], g_colmin_cta[(i + j) * K + t]);
        }
        for (; i < nsm; ++i) m[0] = min(m[0], g_colmin_cta[i * K + t]);
        #pragma unroll
        for (int j = 1; j < 8; ++j) m[0] = min(m[0], m[j]);

        red[t] = sqrtf(fmaxf(__uint_as_float(m[0]), 1e-12f));
        __syncthreads();
        for (int st = 256; st > 0; st >>= 1) {
            if (t < st) red[t] += red[t + st];
            __syncthreads();
        }

        if (t == 0) {
            float pdl = 0.5f * (rowsum / (float)N_ROWS) + 0.5f * (red[0] / (float)K);
            out[CVAE_OFF] = recon[0] + 0.5f * kl[0] + mmd[0];
            out[PDL_OFF]  = pdl;
        }
    }
}

// ---------------------------------------------------------------------------
extern "C" void kernel_launch(void* const* d_in, const int* in_sizes, int n_in,
                              void* d_out, int out_size) {
    const float* x     = (const float*)d_in[0];
    const float* W     = (const float*)d_in[1];
    const float* recon = (const float*)d_in[2];
    const float* kl    = (const float*)d_in[3];
    const float* mmd   = (const float*)d_in[4];
    float* out = (float*)d_out;

    static int nsm = 0;
    if (nsm == 0) {
        cudaDeviceGetAttribute(&nsm, cudaDevAttrMultiProcessorCount, 0);
        if (nsm <= 0) nsm = 148;
        if (nsm > MAXCTA) nsm = MAXCTA;
        cudaFuncSetAttribute(swav_main_kernel,
                             cudaFuncAttributeMaxDynamicSharedMemorySize, SMEM_TOTAL);
    }

    swav_main_kernel<<<nsm, THREADS, SMEM_TOTAL>>>(x, W, recon, kl, mmd, out, nsm);
}